// round 8
// baseline (speedup 1.0000x reference)
#include <cuda_runtime.h>
#include <math.h>

#define Nn 20000
#define Ee 320000
#define IND 128
#define HID 256
#define HEADS 4
#define HD 64
#define OUTD 128
#define NEG_SLOPE 0.2f
#define BN_EPS 1e-5f

// ---------------- scratch (static device allocations; allowed) ----------------
__device__ float g_h1[Nn * HID];       // layer1 GEMM out, later reused for normalized h
__device__ float g_out1[Nn * HID];     // layer1 GAT out (pre-BN)
__device__ float g_h2[Nn * OUTD];      // layer2 GEMM out
__device__ float g_out2[Nn * OUTD];    // layer2 GAT out (pre-BN)
__device__ float g_as1[Nn * HEADS], g_ad1[Nn * HEADS];
__device__ float g_as2[Nn], g_ad2[Nn];
__device__ int   g_src[Ee];
__device__ int   g_dst[Ee];
__device__ int   g_deg[Nn];
__device__ int   g_rowstart[Nn + 1];
__device__ int   g_cursor[Nn];
__device__ int   g_csr[Ee];
__device__ int   g_is32;
__device__ float g_sum1[HID], g_sq1[HID], g_mean1[HID], g_rstd1[HID];
__device__ float g_sum2[OUTD], g_sq2[OUTD], g_mean2[OUTD], g_rstd2[OUTD];

// ---------------- dtype detect + decode ----------------
// If edge_index is truly int64, every 8-byte value is in [0, Nn). If it is
// int32 (JAX x64-disabled demotion), 8-byte reads fuse two random node ids and
// are >= 2^32 (or otherwise out of range) with overwhelming probability.
__global__ void k_detect(const void* __restrict__ ei_raw) {
    if (threadIdx.x == 0 && blockIdx.x == 0) {
        const long long* p = (const long long*)ei_raw;
        int bad = 0;
        for (int i = 0; i < 1024; ++i) {
            long long v = p[i];
            if (v < 0 || v >= Nn) bad = 1;
        }
        g_is32 = bad;
    }
}

__global__ void k_decode(const void* __restrict__ ei_raw) {
    int i = blockIdx.x * blockDim.x + threadIdx.x;
    if (i >= Ee) return;
    int s, d;
    if (g_is32) {
        const int* p = (const int*)ei_raw;
        s = p[i];
        d = p[Ee + i];
    } else {
        const long long* p = (const long long*)ei_raw;
        s = (int)p[i];
        d = (int)p[Ee + i];
    }
    // defensive clamp: no index may ever leave [0, Nn)
    s = min(max(s, 0), Nn - 1);
    d = min(max(d, 0), Nn - 1);
    g_src[i] = s;
    g_dst[i] = d;
}

// ---------------- init ----------------
__global__ void k_zero() {
    int i = blockIdx.x * blockDim.x + threadIdx.x;
    if (i < Nn) g_deg[i] = 0;
    if (i < HID) { g_sum1[i] = 0.f; g_sq1[i] = 0.f; }
    if (i < OUTD) { g_sum2[i] = 0.f; g_sq2[i] = 0.f; }
}

// ---------------- CSR build (by dst) ----------------
__global__ void k_count() {
    int i = blockIdx.x * blockDim.x + threadIdx.x;
    if (i < Ee) atomicAdd(&g_deg[g_dst[i]], 1);
}

__global__ void k_scan() {  // single block, 1024 threads
    __shared__ int sh[1024];
    int t = threadIdx.x;
    int carry = 0;
    for (int base = 0; base < Nn; base += 1024) {
        __syncthreads();
        int v = (base + t < Nn) ? g_deg[base + t] : 0;
        sh[t] = v;
        __syncthreads();
        for (int off = 1; off < 1024; off <<= 1) {
            int x = (t >= off) ? sh[t - off] : 0;
            __syncthreads();
            sh[t] += x;
            __syncthreads();
        }
        int incl = sh[t];
        if (base + t < Nn) {
            int ex = carry + incl - v;
            g_rowstart[base + t] = ex;
            g_cursor[base + t] = ex;
        }
        carry += sh[1023];
    }
    if (t == 0) g_rowstart[Nn] = carry;
}

__global__ void k_scatter() {
    int i = blockIdx.x * blockDim.x + threadIdx.x;
    if (i < Ee) {
        int pos = atomicAdd(&g_cursor[g_dst[i]], 1);
        g_csr[pos] = g_src[i];
    }
}

// ---------------- SGEMM (64x64 tile, 16x16 threads, 4x4 microtile) ----------------
__device__ __forceinline__ void sgemm_body(const float* __restrict__ A,
                                           const float* __restrict__ B,
                                           float* __restrict__ C,
                                           int M, int N, int K) {
    __shared__ float As[16][68];
    __shared__ float Bs[16][64];
    int tx = threadIdx.x, ty = threadIdx.y;
    int tid = ty * 16 + tx;
    int row0 = blockIdx.x * 64, col0 = blockIdx.y * 64;
    int ar = tid >> 2;
    int ac = (tid & 3) * 4;
    int br = tid >> 4;
    int bc = (tid & 15) * 4;
    float acc[4][4];
#pragma unroll
    for (int i = 0; i < 4; i++)
#pragma unroll
        for (int j = 0; j < 4; j++) acc[i][j] = 0.f;

    for (int k0 = 0; k0 < K; k0 += 16) {
        float4 av = make_float4(0.f, 0.f, 0.f, 0.f);
        if (row0 + ar < M)
            av = *(const float4*)(A + (size_t)(row0 + ar) * K + k0 + ac);
        As[ac][ar] = av.x; As[ac + 1][ar] = av.y; As[ac + 2][ar] = av.z; As[ac + 3][ar] = av.w;
        float4 bv = *(const float4*)(B + (size_t)(k0 + br) * N + col0 + bc);
        *(float4*)&Bs[br][bc] = bv;
        __syncthreads();
#pragma unroll
        for (int k = 0; k < 16; k++) {
            float4 a = *(const float4*)&As[k][ty * 4];
            float4 b = *(const float4*)&Bs[k][tx * 4];
            acc[0][0] += a.x * b.x; acc[0][1] += a.x * b.y; acc[0][2] += a.x * b.z; acc[0][3] += a.x * b.w;
            acc[1][0] += a.y * b.x; acc[1][1] += a.y * b.y; acc[1][2] += a.y * b.z; acc[1][3] += a.y * b.w;
            acc[2][0] += a.z * b.x; acc[2][1] += a.z * b.y; acc[2][2] += a.z * b.z; acc[2][3] += a.z * b.w;
            acc[3][0] += a.w * b.x; acc[3][1] += a.w * b.y; acc[3][2] += a.w * b.z; acc[3][3] += a.w * b.w;
        }
        __syncthreads();
    }
#pragma unroll
    for (int i = 0; i < 4; i++) {
        int r = row0 + ty * 4 + i;
        if (r < M) {
            float4 o = make_float4(acc[i][0], acc[i][1], acc[i][2], acc[i][3]);
            *(float4*)(C + (size_t)r * N + col0 + tx * 4) = o;
        }
    }
}

__global__ void k_gemm1(const float* __restrict__ x, const float* __restrict__ W1) {
    sgemm_body(x, W1, g_h1, Nn, HID, IND);
}
__global__ void k_gemm2(const float* __restrict__ W2) {
    sgemm_body(g_h1, W2, g_h2, Nn, OUTD, HID);
}

// ---------------- attention coefficients ----------------
__global__ void k_alpha1(const float* __restrict__ attS, const float* __restrict__ attD) {
    int gw = (blockIdx.x * blockDim.x + threadIdx.x) >> 5;
    int l = threadIdx.x & 31;
    if (gw >= Nn) return;
    const float* row = g_h1 + (size_t)gw * HID;
    float4 v0 = *(const float4*)(row + l * 8);
    float4 v1 = *(const float4*)(row + l * 8 + 4);
    float4 s0 = *(const float4*)(attS + l * 8);
    float4 s1 = *(const float4*)(attS + l * 8 + 4);
    float4 d0 = *(const float4*)(attD + l * 8);
    float4 d1 = *(const float4*)(attD + l * 8 + 4);
    float ps = v0.x * s0.x + v0.y * s0.y + v0.z * s0.z + v0.w * s0.w +
               v1.x * s1.x + v1.y * s1.y + v1.z * s1.z + v1.w * s1.w;
    float pd = v0.x * d0.x + v0.y * d0.y + v0.z * d0.z + v0.w * d0.w +
               v1.x * d1.x + v1.y * d1.y + v1.z * d1.z + v1.w * d1.w;
    for (int off = 4; off; off >>= 1) {
        ps += __shfl_down_sync(0xffffffffu, ps, off, 8);
        pd += __shfl_down_sync(0xffffffffu, pd, off, 8);
    }
    if ((l & 7) == 0) {
        g_as1[gw * HEADS + (l >> 3)] = ps;
        g_ad1[gw * HEADS + (l >> 3)] = pd;
    }
}

__global__ void k_alpha2(const float* __restrict__ attS, const float* __restrict__ attD) {
    int gw = (blockIdx.x * blockDim.x + threadIdx.x) >> 5;
    int l = threadIdx.x & 31;
    if (gw >= Nn) return;
    const float* row = g_h2 + (size_t)gw * OUTD;
    float4 v = *(const float4*)(row + l * 4);
    float4 s = *(const float4*)(attS + l * 4);
    float4 d = *(const float4*)(attD + l * 4);
    float ps = v.x * s.x + v.y * s.y + v.z * s.z + v.w * s.w;
    float pd = v.x * d.x + v.y * d.y + v.z * d.z + v.w * d.w;
    for (int off = 16; off; off >>= 1) {
        ps += __shfl_xor_sync(0xffffffffu, ps, off);
        pd += __shfl_xor_sync(0xffffffffu, pd, off);
    }
    if (l == 0) { g_as2[gw] = ps; g_ad2[gw] = pd; }
}

__device__ __forceinline__ float leaky(float e) { return e > 0.f ? e : NEG_SLOPE * e; }

// ---------------- layer 1 aggregation: block=node, warp=head ----------------
__global__ void k_agg1(const float* __restrict__ bias) {
    int n = blockIdx.x;
    int w = threadIdx.x >> 5, l = threadIdx.x & 31;
    int start = g_rowstart[n], end = g_rowstart[n + 1];
    float ad = g_ad1[n * HEADS + w];
    float e_self = leaky(g_as1[n * HEADS + w] + ad);
    float m = e_self;
    for (int j = start + l; j < end; j += 32) {
        int s = g_csr[j];
        m = fmaxf(m, leaky(g_as1[s * HEADS + w] + ad));
    }
    for (int off = 16; off; off >>= 1) m = fmaxf(m, __shfl_xor_sync(0xffffffffu, m, off));

    float ex_self = expf(e_self - m);
    const float* hself = g_h1 + (size_t)n * HID + w * HD + 2 * l;
    float2 acc;
    acc.x = ex_self * hself[0];
    acc.y = ex_self * hself[1];
    float dpart = 0.f;
    for (int base = start; base < end; base += 32) {
        int idx = base + l;
        int valid = idx < end;
        int s = valid ? g_csr[idx] : 0;
        float ex = 0.f;
        if (valid) ex = expf(leaky(g_as1[s * HEADS + w] + ad) - m);
        dpart += ex;
        int cnt = min(32, end - base);
        for (int j2 = 0; j2 < cnt; ++j2) {
            float exj = __shfl_sync(0xffffffffu, ex, j2);
            int sj = __shfl_sync(0xffffffffu, s, j2);
            float2 hv = *(const float2*)(g_h1 + (size_t)sj * HID + w * HD + 2 * l);
            acc.x += exj * hv.x;
            acc.y += exj * hv.y;
        }
    }
    for (int off = 16; off; off >>= 1) dpart += __shfl_xor_sync(0xffffffffu, dpart, off);
    float inv = 1.f / (dpart + ex_self + 1e-16f);
    int o = n * HID + w * HD + 2 * l;
    g_out1[o] = acc.x * inv + bias[w * HD + 2 * l];
    g_out1[o + 1] = acc.y * inv + bias[w * HD + 2 * l + 1];
}

// ---------------- layer 2 aggregation: warp=node ----------------
__global__ void k_agg2(const float* __restrict__ bias) {
    int n = (blockIdx.x * blockDim.x + threadIdx.x) >> 5;
    int l = threadIdx.x & 31;
    if (n >= Nn) return;
    int start = g_rowstart[n], end = g_rowstart[n + 1];
    float ad = g_ad2[n];
    float e_self = leaky(g_as2[n] + ad);
    float m = e_self;
    for (int j = start + l; j < end; j += 32)
        m = fmaxf(m, leaky(g_as2[g_csr[j]] + ad));
    for (int off = 16; off; off >>= 1) m = fmaxf(m, __shfl_xor_sync(0xffffffffu, m, off));

    float ex_self = expf(e_self - m);
    float4 hv = *(const float4*)(g_h2 + (size_t)n * OUTD + l * 4);
    float4 acc;
    acc.x = ex_self * hv.x; acc.y = ex_self * hv.y; acc.z = ex_self * hv.z; acc.w = ex_self * hv.w;
    float dpart = 0.f;
    for (int base = start; base < end; base += 32) {
        int idx = base + l;
        int valid = idx < end;
        int s = valid ? g_csr[idx] : 0;
        float ex = 0.f;
        if (valid) ex = expf(leaky(g_as2[s] + ad) - m);
        dpart += ex;
        int cnt = min(32, end - base);
        for (int j2 = 0; j2 < cnt; ++j2) {
            float exj = __shfl_sync(0xffffffffu, ex, j2);
            int sj = __shfl_sync(0xffffffffu, s, j2);
            float4 v = *(const float4*)(g_h2 + (size_t)sj * OUTD + l * 4);
            acc.x += exj * v.x; acc.y += exj * v.y; acc.z += exj * v.z; acc.w += exj * v.w;
        }
    }
    for (int off = 16; off; off >>= 1) dpart += __shfl_xor_sync(0xffffffffu, dpart, off);
    float inv = 1.f / (dpart + ex_self + 1e-16f);
    int o = n * OUTD + l * 4;
    g_out2[o]     = acc.x * inv + bias[l * 4];
    g_out2[o + 1] = acc.y * inv + bias[l * 4 + 1];
    g_out2[o + 2] = acc.z * inv + bias[l * 4 + 2];
    g_out2[o + 3] = acc.w * inv + bias[l * 4 + 3];
}

// ---------------- batch norm ----------------
__device__ __forceinline__ void bnstats_body(const float* __restrict__ X, float* sum, float* sq, int C) {
    int t = threadIdx.x;
    float s = 0.f, q = 0.f;
    for (int r = blockIdx.x; r < Nn; r += gridDim.x) {
        float v = X[(size_t)r * C + t];
        s += v; q += v * v;
    }
    atomicAdd(&sum[t], s);
    atomicAdd(&sq[t], q);
}
__global__ void k_bnstats1() { bnstats_body(g_out1, g_sum1, g_sq1, HID); }
__global__ void k_bnstats2() { bnstats_body(g_out2, g_sum2, g_sq2, OUTD); }

__global__ void k_bnfin() {
    int t = threadIdx.x;
    if (t < HID) {
        float mu = g_sum1[t] * (1.f / Nn);
        float var = g_sq1[t] * (1.f / Nn) - mu * mu;
        g_mean1[t] = mu;
        g_rstd1[t] = rsqrtf(fmaxf(var, 0.f) + BN_EPS);
    }
    if (t < OUTD) {
        float mu = g_sum2[t] * (1.f / Nn);
        float var = g_sq2[t] * (1.f / Nn) - mu * mu;
        g_mean2[t] = mu;
        g_rstd2[t] = rsqrtf(fmaxf(var, 0.f) + BN_EPS);
    }
}

__global__ void k_bnapply_elu(const float* __restrict__ gamma, const float* __restrict__ beta) {
    for (int i = blockIdx.x * blockDim.x + threadIdx.x; i < Nn * HID; i += gridDim.x * blockDim.x) {
        int c = i & (HID - 1);
        float v = (g_out1[i] - g_mean1[c]) * g_rstd1[c] * gamma[c] + beta[c];
        g_h1[i] = v > 0.f ? v : expm1f(v);   // ELU, overwrite g_h1 (h1 dead here)
    }
}

__global__ void k_bnapply_out(const float* __restrict__ gamma, const float* __restrict__ beta,
                              float* __restrict__ out) {
    for (int i = blockIdx.x * blockDim.x + threadIdx.x; i < Nn * OUTD; i += gridDim.x * blockDim.x) {
        int c = i & (OUTD - 1);
        out[i] = (g_out2[i] - g_mean2[c]) * g_rstd2[c] * gamma[c] + beta[c];
    }
}

// ---------------- launch ----------------
extern "C" void kernel_launch(void* const* d_in, const int* in_sizes, int n_in,
                              void* d_out, int out_size) {
    const float* x      = (const float*)d_in[0];
    const void*  ei     = d_in[1];
    const float* W1     = (const float*)d_in[2];
    const float* attS1  = (const float*)d_in[3];
    const float* attD1  = (const float*)d_in[4];
    const float* bias1  = (const float*)d_in[5];
    const float* g1     = (const float*)d_in[6];
    const float* b1     = (const float*)d_in[7];
    const float* W2     = (const float*)d_in[8];
    const float* attS2  = (const float*)d_in[9];
    const float* attD2  = (const float*)d_in[10];
    const float* bias2  = (const float*)d_in[11];
    const float* g2     = (const float*)d_in[12];
    const float* b2     = (const float*)d_in[13];
    float* out = (float*)d_out;

    // dtype detect + decode + init + CSR build
    k_detect<<<1, 32>>>(ei);
    k_decode<<<(Ee + 255) / 256, 256>>>(ei);
    k_zero<<<(Nn + 255) / 256, 256>>>();
    k_count<<<(Ee + 255) / 256, 256>>>();
    k_scan<<<1, 1024>>>();
    k_scatter<<<(Ee + 255) / 256, 256>>>();

    // layer 1
    k_gemm1<<<dim3((Nn + 63) / 64, HID / 64), dim3(16, 16)>>>(x, W1);
    k_alpha1<<<(Nn + 3) / 4, 128>>>(attS1, attD1);
    k_agg1<<<Nn, 128>>>(bias1);
    k_bnstats1<<<256, HID>>>();
    k_bnfin<<<1, 256>>>();            // layer-1 stats valid here; layer-2 recomputed later
    k_bnapply_elu<<<2048, 256>>>(g1, b1);

    // layer 2
    k_gemm2<<<dim3((Nn + 63) / 64, OUTD / 64), dim3(16, 16)>>>(W2);
    k_alpha2<<<(Nn + 3) / 4, 128>>>(attS2, attD2);
    k_agg2<<<(Nn + 3) / 4, 128>>>(bias2);
    k_bnstats2<<<256, OUTD>>>();
    k_bnfin<<<1, 256>>>();            // now layer-2 stats valid
    k_bnapply_out<<<2048, 256>>>(g2, b2, out);
}

// round 9
// speedup vs baseline: 1.0489x; 1.0489x over previous
#include <cuda_runtime.h>
#include <math.h>

#define Nn 20000
#define Ee 320000
#define IND 128
#define HID 256
#define HEADS 4
#define HD 64
#define OUTD 128
#define NEG_SLOPE 0.2f
#define BN_EPS 1e-5f

typedef unsigned long long u64;

// ---------------- scratch (static device allocations; allowed) ----------------
__device__ float g_h1[Nn * HID];       // layer1 GEMM out, later reused for normalized h
__device__ float g_out1[Nn * HID];     // layer1 GAT out (pre-BN)
__device__ float g_h2[Nn * OUTD];      // layer2 GEMM out
__device__ float g_out2[Nn * OUTD];    // layer2 GAT out (pre-BN)
__device__ float g_as1[Nn * HEADS], g_ad1[Nn * HEADS];
__device__ float g_as2[Nn], g_ad2[Nn];
__device__ int   g_src[Ee];
__device__ int   g_dst[Ee];
__device__ int   g_deg[Nn];
__device__ int   g_rowstart[Nn + 1];
__device__ int   g_cursor[Nn];
__device__ int   g_csr[Ee];
__device__ int   g_is32;
__device__ float g_sum1[HID], g_sq1[HID], g_mean1[HID], g_rstd1[HID];
__device__ float g_sum2[OUTD], g_sq2[OUTD], g_mean2[OUTD], g_rstd2[OUTD];

// ---------------- packed f32x2 helpers ----------------
__device__ __forceinline__ u64 pack2(float lo, float hi) {
    u64 r; asm("mov.b64 %0, {%1, %2};" : "=l"(r) : "f"(lo), "f"(hi)); return r;
}
__device__ __forceinline__ void unpack2(u64 v, float& lo, float& hi) {
    asm("mov.b64 {%0, %1}, %2;" : "=f"(lo), "=f"(hi) : "l"(v));
}
__device__ __forceinline__ void fma2(u64& d, u64 a, u64 b) {
    asm("fma.rn.f32x2 %0, %1, %2, %3;" : "=l"(d) : "l"(a), "l"(b), "l"(d));
}

// ---------------- dtype detect + decode ----------------
__global__ void k_detect(const void* __restrict__ ei_raw) {
    if (threadIdx.x == 0 && blockIdx.x == 0) {
        const long long* p = (const long long*)ei_raw;
        int bad = 0;
        for (int i = 0; i < 1024; ++i) {
            long long v = p[i];
            if (v < 0 || v >= Nn) bad = 1;
        }
        g_is32 = bad;
    }
}

__global__ void k_decode(const void* __restrict__ ei_raw) {
    int i = blockIdx.x * blockDim.x + threadIdx.x;
    if (i >= Ee) return;
    int s, d;
    if (g_is32) {
        const int* p = (const int*)ei_raw;
        s = p[i];
        d = p[Ee + i];
    } else {
        const long long* p = (const long long*)ei_raw;
        s = (int)p[i];
        d = (int)p[Ee + i];
    }
    s = min(max(s, 0), Nn - 1);
    d = min(max(d, 0), Nn - 1);
    g_src[i] = s;
    g_dst[i] = d;
}

// ---------------- init ----------------
__global__ void k_zero() {
    int i = blockIdx.x * blockDim.x + threadIdx.x;
    if (i < Nn) g_deg[i] = 0;
    if (i < HID) { g_sum1[i] = 0.f; g_sq1[i] = 0.f; }
    if (i < OUTD) { g_sum2[i] = 0.f; g_sq2[i] = 0.f; }
}

// ---------------- CSR build (by dst) ----------------
__global__ void k_count() {
    int i = blockIdx.x * blockDim.x + threadIdx.x;
    if (i < Ee) atomicAdd(&g_deg[g_dst[i]], 1);
}

__global__ void k_scan() {  // single block, 1024 threads
    __shared__ int sh[1024];
    int t = threadIdx.x;
    int carry = 0;
    for (int base = 0; base < Nn; base += 1024) {
        __syncthreads();
        int v = (base + t < Nn) ? g_deg[base + t] : 0;
        sh[t] = v;
        __syncthreads();
        for (int off = 1; off < 1024; off <<= 1) {
            int x = (t >= off) ? sh[t - off] : 0;
            __syncthreads();
            sh[t] += x;
            __syncthreads();
        }
        int incl = sh[t];
        if (base + t < Nn) {
            int ex = carry + incl - v;
            g_rowstart[base + t] = ex;
            g_cursor[base + t] = ex;
        }
        carry += sh[1023];
    }
    if (t == 0) g_rowstart[Nn] = carry;
}

__global__ void k_scatter() {
    int i = blockIdx.x * blockDim.x + threadIdx.x;
    if (i < Ee) {
        int pos = atomicAdd(&g_cursor[g_dst[i]], 1);
        g_csr[pos] = g_src[i];
    }
}

// ---------------- SGEMM (64x64 tile, 16x16 threads, 4x4 microtile, f32x2 FMA,
//                  register-staged global prefetch) ----------------
__device__ __forceinline__ void sgemm_body(const float* __restrict__ A,
                                           const float* __restrict__ B,
                                           float* __restrict__ C,
                                           int M, int N, int K) {
    __shared__ float As[16][68];   // [k][row], transposed on store
    __shared__ float Bs[16][64];   // [k][col]
    int tx = threadIdx.x, ty = threadIdx.y;
    int tid = ty * 16 + tx;
    int row0 = blockIdx.x * 64, col0 = blockIdx.y * 64;
    int ar = tid >> 2;
    int ac = (tid & 3) * 4;
    int br = tid >> 4;
    int bc = (tid & 15) * 4;

    // paired-row accumulators: accp[p][j] = (c[2p][j], c[2p+1][j])
    u64 accp[2][4];
#pragma unroll
    for (int p = 0; p < 2; p++)
#pragma unroll
        for (int j = 0; j < 4; j++) accp[p][j] = 0ull;

    // prologue: load tile 0 into registers
    float4 av = make_float4(0.f, 0.f, 0.f, 0.f);
    if (row0 + ar < M)
        av = *(const float4*)(A + (size_t)(row0 + ar) * K + ac);
    float4 bv = *(const float4*)(B + (size_t)br * N + col0 + bc);

    for (int k0 = 0; k0 < K; k0 += 16) {
        // stage registers -> shared
        As[ac][ar] = av.x; As[ac + 1][ar] = av.y; As[ac + 2][ar] = av.z; As[ac + 3][ar] = av.w;
        *(float4*)&Bs[br][bc] = bv;
        __syncthreads();

        // prefetch next tile into registers while computing this one
        if (k0 + 16 < K) {
            av = make_float4(0.f, 0.f, 0.f, 0.f);
            if (row0 + ar < M)
                av = *(const float4*)(A + (size_t)(row0 + ar) * K + k0 + 16 + ac);
            bv = *(const float4*)(B + (size_t)(k0 + 16 + br) * N + col0 + bc);
        }

#pragma unroll
        for (int k = 0; k < 16; k++) {
            u64 a01 = *(const u64*)&As[k][ty * 4];
            u64 a23 = *(const u64*)&As[k][ty * 4 + 2];
            float4 b = *(const float4*)&Bs[k][tx * 4];
            u64 b0 = pack2(b.x, b.x);
            u64 b1 = pack2(b.y, b.y);
            u64 b2 = pack2(b.z, b.z);
            u64 b3 = pack2(b.w, b.w);
            fma2(accp[0][0], a01, b0); fma2(accp[0][1], a01, b1);
            fma2(accp[0][2], a01, b2); fma2(accp[0][3], a01, b3);
            fma2(accp[1][0], a23, b0); fma2(accp[1][1], a23, b1);
            fma2(accp[1][2], a23, b2); fma2(accp[1][3], a23, b3);
        }
        __syncthreads();
    }

#pragma unroll
    for (int p = 0; p < 2; p++) {
        float lo0, hi0, lo1, hi1, lo2, hi2, lo3, hi3;
        unpack2(accp[p][0], lo0, hi0);
        unpack2(accp[p][1], lo1, hi1);
        unpack2(accp[p][2], lo2, hi2);
        unpack2(accp[p][3], lo3, hi3);
        int r_lo = row0 + ty * 4 + 2 * p;
        if (r_lo < M)
            *(float4*)(C + (size_t)r_lo * N + col0 + tx * 4) = make_float4(lo0, lo1, lo2, lo3);
        int r_hi = r_lo + 1;
        if (r_hi < M)
            *(float4*)(C + (size_t)r_hi * N + col0 + tx * 4) = make_float4(hi0, hi1, hi2, hi3);
    }
}

__global__ void __launch_bounds__(256) k_gemm1(const float* __restrict__ x, const float* __restrict__ W1) {
    sgemm_body(x, W1, g_h1, Nn, HID, IND);
}
__global__ void __launch_bounds__(256) k_gemm2(const float* __restrict__ W2) {
    sgemm_body(g_h1, W2, g_h2, Nn, OUTD, HID);
}

// ---------------- attention coefficients ----------------
__global__ void k_alpha1(const float* __restrict__ attS, const float* __restrict__ attD) {
    int gw = (blockIdx.x * blockDim.x + threadIdx.x) >> 5;
    int l = threadIdx.x & 31;
    if (gw >= Nn) return;
    const float* row = g_h1 + (size_t)gw * HID;
    float4 v0 = *(const float4*)(row + l * 8);
    float4 v1 = *(const float4*)(row + l * 8 + 4);
    float4 s0 = *(const float4*)(attS + l * 8);
    float4 s1 = *(const float4*)(attS + l * 8 + 4);
    float4 d0 = *(const float4*)(attD + l * 8);
    float4 d1 = *(const float4*)(attD + l * 8 + 4);
    float ps = v0.x * s0.x + v0.y * s0.y + v0.z * s0.z + v0.w * s0.w +
               v1.x * s1.x + v1.y * s1.y + v1.z * s1.z + v1.w * s1.w;
    float pd = v0.x * d0.x + v0.y * d0.y + v0.z * d0.z + v0.w * d0.w +
               v1.x * d1.x + v1.y * d1.y + v1.z * d1.z + v1.w * d1.w;
    for (int off = 4; off; off >>= 1) {
        ps += __shfl_down_sync(0xffffffffu, ps, off, 8);
        pd += __shfl_down_sync(0xffffffffu, pd, off, 8);
    }
    if ((l & 7) == 0) {
        g_as1[gw * HEADS + (l >> 3)] = ps;
        g_ad1[gw * HEADS + (l >> 3)] = pd;
    }
}

__global__ void k_alpha2(const float* __restrict__ attS, const float* __restrict__ attD) {
    int gw = (blockIdx.x * blockDim.x + threadIdx.x) >> 5;
    int l = threadIdx.x & 31;
    if (gw >= Nn) return;
    const float* row = g_h2 + (size_t)gw * OUTD;
    float4 v = *(const float4*)(row + l * 4);
    float4 s = *(const float4*)(attS + l * 4);
    float4 d = *(const float4*)(attD + l * 4);
    float ps = v.x * s.x + v.y * s.y + v.z * s.z + v.w * s.w;
    float pd = v.x * d.x + v.y * d.y + v.z * d.z + v.w * d.w;
    for (int off = 16; off; off >>= 1) {
        ps += __shfl_xor_sync(0xffffffffu, ps, off);
        pd += __shfl_xor_sync(0xffffffffu, pd, off);
    }
    if (l == 0) { g_as2[gw] = ps; g_ad2[gw] = pd; }
}

__device__ __forceinline__ float leaky(float e) { return e > 0.f ? e : NEG_SLOPE * e; }

// ---------------- layer 1 aggregation: block=node, warp=head ----------------
__global__ void k_agg1(const float* __restrict__ bias) {
    int n = blockIdx.x;
    int w = threadIdx.x >> 5, l = threadIdx.x & 31;
    int start = g_rowstart[n], end = g_rowstart[n + 1];
    float ad = g_ad1[n * HEADS + w];
    float e_self = leaky(g_as1[n * HEADS + w] + ad);
    float m = e_self;
    for (int j = start + l; j < end; j += 32) {
        int s = g_csr[j];
        m = fmaxf(m, leaky(g_as1[s * HEADS + w] + ad));
    }
    for (int off = 16; off; off >>= 1) m = fmaxf(m, __shfl_xor_sync(0xffffffffu, m, off));

    float ex_self = expf(e_self - m);
    const float* hself = g_h1 + (size_t)n * HID + w * HD + 2 * l;
    float2 acc;
    acc.x = ex_self * hself[0];
    acc.y = ex_self * hself[1];
    float dpart = 0.f;
    for (int base = start; base < end; base += 32) {
        int idx = base + l;
        int valid = idx < end;
        int s = valid ? g_csr[idx] : 0;
        float ex = 0.f;
        if (valid) ex = expf(leaky(g_as1[s * HEADS + w] + ad) - m);
        dpart += ex;
        int cnt = min(32, end - base);
        for (int j2 = 0; j2 < cnt; ++j2) {
            float exj = __shfl_sync(0xffffffffu, ex, j2);
            int sj = __shfl_sync(0xffffffffu, s, j2);
            float2 hv = *(const float2*)(g_h1 + (size_t)sj * HID + w * HD + 2 * l);
            acc.x += exj * hv.x;
            acc.y += exj * hv.y;
        }
    }
    for (int off = 16; off; off >>= 1) dpart += __shfl_xor_sync(0xffffffffu, dpart, off);
    float inv = 1.f / (dpart + ex_self + 1e-16f);
    int o = n * HID + w * HD + 2 * l;
    g_out1[o] = acc.x * inv + bias[w * HD + 2 * l];
    g_out1[o + 1] = acc.y * inv + bias[w * HD + 2 * l + 1];
}

// ---------------- layer 2 aggregation: warp=node ----------------
__global__ void k_agg2(const float* __restrict__ bias) {
    int n = (blockIdx.x * blockDim.x + threadIdx.x) >> 5;
    int l = threadIdx.x & 31;
    if (n >= Nn) return;
    int start = g_rowstart[n], end = g_rowstart[n + 1];
    float ad = g_ad2[n];
    float e_self = leaky(g_as2[n] + ad);
    float m = e_self;
    for (int j = start + l; j < end; j += 32)
        m = fmaxf(m, leaky(g_as2[g_csr[j]] + ad));
    for (int off = 16; off; off >>= 1) m = fmaxf(m, __shfl_xor_sync(0xffffffffu, m, off));

    float ex_self = expf(e_self - m);
    float4 hv = *(const float4*)(g_h2 + (size_t)n * OUTD + l * 4);
    float4 acc;
    acc.x = ex_self * hv.x; acc.y = ex_self * hv.y; acc.z = ex_self * hv.z; acc.w = ex_self * hv.w;
    float dpart = 0.f;
    for (int base = start; base < end; base += 32) {
        int idx = base + l;
        int valid = idx < end;
        int s = valid ? g_csr[idx] : 0;
        float ex = 0.f;
        if (valid) ex = expf(leaky(g_as2[s] + ad) - m);
        dpart += ex;
        int cnt = min(32, end - base);
        for (int j2 = 0; j2 < cnt; ++j2) {
            float exj = __shfl_sync(0xffffffffu, ex, j2);
            int sj = __shfl_sync(0xffffffffu, s, j2);
            float4 v = *(const float4*)(g_h2 + (size_t)sj * OUTD + l * 4);
            acc.x += exj * v.x; acc.y += exj * v.y; acc.z += exj * v.z; acc.w += exj * v.w;
        }
    }
    for (int off = 16; off; off >>= 1) dpart += __shfl_xor_sync(0xffffffffu, dpart, off);
    float inv = 1.f / (dpart + ex_self + 1e-16f);
    int o = n * OUTD + l * 4;
    g_out2[o]     = acc.x * inv + bias[l * 4];
    g_out2[o + 1] = acc.y * inv + bias[l * 4 + 1];
    g_out2[o + 2] = acc.z * inv + bias[l * 4 + 2];
    g_out2[o + 3] = acc.w * inv + bias[l * 4 + 3];
}

// ---------------- batch norm ----------------
__device__ __forceinline__ void bnstats_body(const float* __restrict__ X, float* sum, float* sq, int C) {
    int t = threadIdx.x;
    float s = 0.f, q = 0.f;
    for (int r = blockIdx.x; r < Nn; r += gridDim.x) {
        float v = X[(size_t)r * C + t];
        s += v; q += v * v;
    }
    atomicAdd(&sum[t], s);
    atomicAdd(&sq[t], q);
}
__global__ void k_bnstats1() { bnstats_body(g_out1, g_sum1, g_sq1, HID); }
__global__ void k_bnstats2() { bnstats_body(g_out2, g_sum2, g_sq2, OUTD); }

__global__ void k_bnfin() {
    int t = threadIdx.x;
    if (t < HID) {
        float mu = g_sum1[t] * (1.f / Nn);
        float var = g_sq1[t] * (1.f / Nn) - mu * mu;
        g_mean1[t] = mu;
        g_rstd1[t] = rsqrtf(fmaxf(var, 0.f) + BN_EPS);
    }
    if (t < OUTD) {
        float mu = g_sum2[t] * (1.f / Nn);
        float var = g_sq2[t] * (1.f / Nn) - mu * mu;
        g_mean2[t] = mu;
        g_rstd2[t] = rsqrtf(fmaxf(var, 0.f) + BN_EPS);
    }
}

__global__ void k_bnapply_elu(const float* __restrict__ gamma, const float* __restrict__ beta) {
    for (int i = blockIdx.x * blockDim.x + threadIdx.x; i < Nn * HID; i += gridDim.x * blockDim.x) {
        int c = i & (HID - 1);
        float v = (g_out1[i] - g_mean1[c]) * g_rstd1[c] * gamma[c] + beta[c];
        g_h1[i] = v > 0.f ? v : expm1f(v);   // ELU, overwrite g_h1 (h1 dead here)
    }
}

__global__ void k_bnapply_out(const float* __restrict__ gamma, const float* __restrict__ beta,
                              float* __restrict__ out) {
    for (int i = blockIdx.x * blockDim.x + threadIdx.x; i < Nn * OUTD; i += gridDim.x * blockDim.x) {
        int c = i & (OUTD - 1);
        out[i] = (g_out2[i] - g_mean2[c]) * g_rstd2[c] * gamma[c] + beta[c];
    }
}

// ---------------- launch ----------------
extern "C" void kernel_launch(void* const* d_in, const int* in_sizes, int n_in,
                              void* d_out, int out_size) {
    const float* x      = (const float*)d_in[0];
    const void*  ei     = d_in[1];
    const float* W1     = (const float*)d_in[2];
    const float* attS1  = (const float*)d_in[3];
    const float* attD1  = (const float*)d_in[4];
    const float* bias1  = (const float*)d_in[5];
    const float* g1     = (const float*)d_in[6];
    const float* b1     = (const float*)d_in[7];
    const float* W2     = (const float*)d_in[8];
    const float* attS2  = (const float*)d_in[9];
    const float* attD2  = (const float*)d_in[10];
    const float* bias2  = (const float*)d_in[11];
    const float* g2     = (const float*)d_in[12];
    const float* b2     = (const float*)d_in[13];
    float* out = (float*)d_out;

    // dtype detect + decode + init + CSR build
    k_detect<<<1, 32>>>(ei);
    k_decode<<<(Ee + 255) / 256, 256>>>(ei);
    k_zero<<<(Nn + 255) / 256, 256>>>();
    k_count<<<(Ee + 255) / 256, 256>>>();
    k_scan<<<1, 1024>>>();
    k_scatter<<<(Ee + 255) / 256, 256>>>();

    // layer 1
    k_gemm1<<<dim3((Nn + 63) / 64, HID / 64), dim3(16, 16)>>>(x, W1);
    k_alpha1<<<(Nn + 3) / 4, 128>>>(attS1, attD1);
    k_agg1<<<Nn, 128>>>(bias1);
    k_bnstats1<<<256, HID>>>();
    k_bnfin<<<1, 256>>>();            // layer-1 stats valid here; layer-2 recomputed later
    k_bnapply_elu<<<2048, 256>>>(g1, b1);

    // layer 2
    k_gemm2<<<dim3((Nn + 63) / 64, OUTD / 64), dim3(16, 16)>>>(W2);
    k_alpha2<<<(Nn + 3) / 4, 128>>>(attS2, attD2);
    k_agg2<<<(Nn + 3) / 4, 128>>>(bias2);
    k_bnstats2<<<256, OUTD>>>();
    k_bnfin<<<1, 256>>>();            // now layer-2 stats valid
    k_bnapply_out<<<2048, 256>>>(g2, b2, out);
}